// round 3
// baseline (speedup 1.0000x reference)
#include <cuda_runtime.h>
#include <cuda_fp16.h>
#include <cstdint>

#define NROW 8192
#define FDIM 512
#define KC   1536   // split-fp16 concatenated K for the WX GEMM
#define NB   640    // padded B cols: 512 feats + 8 dens + 120 zero pad

// ------------------------- scratch (device globals) -------------------------
__device__ __half g_Xc[(size_t)NROW * KC];     // [Xh | Xh | Xl]
__device__ __half g_Wc[(size_t)KC * FDIM];     // [Wh ; Wl ; Wh]  (rows = K)
__device__ float  g_WX[(size_t)NROW * FDIM];   // WX[n][h*64+o]
__device__ float  g_s2[8 * NROW];
__device__ float  g_mx[8];
__device__ __half g_A16[(size_t)NROW * NROW];  // A in fp16 (exact 0/1)
__device__ __half g_B[(size_t)NROW * NB];      // B[j][c] = w*WX (c<512), w (512..519), 0 pad
__device__ float  g_C[(size_t)NROW * NB];      // raw GEMM2 output

// ------------------------- small prep kernels -------------------------
__global__ void k_prepX(const float* __restrict__ X) {
    size_t i = (size_t)blockIdx.x * 256 + threadIdx.x;   // over 8192*512
    size_t n = i >> 9, f = i & 511;
    float v = X[i];
    __half h = __float2half_rn(v);
    float r = v - __half2float(h);
    g_Xc[n * KC + f]        = h;
    g_Xc[n * KC + 512 + f]  = h;
    g_Xc[n * KC + 1024 + f] = __float2half_rn(r);
}

__global__ void k_prepW(const float* __restrict__ kern) {
    size_t i = (size_t)blockIdx.x * 256 + threadIdx.x;   // over 512*512
    int f = (int)(i >> 9), c = (int)(i & 511);
    int h = c >> 6, o = c & 63;
    float v = kern[((size_t)h * 512 + f) * 64 + o];
    __half hh = __float2half_rn(v);
    float r = v - __half2float(hh);
    g_Wc[(size_t)f * FDIM + c]          = hh;
    g_Wc[(size_t)(512 + f) * FDIM + c]  = __float2half_rn(r);
    g_Wc[(size_t)(1024 + f) * FDIM + c] = hh;
}

__global__ void k_s2(const float* __restrict__ attn) {
    int n = blockIdx.x;                 // 8192 blocks, 256 threads = 8 warps
    int h = threadIdx.x >> 5;           // warp == head
    int lane = threadIdx.x & 31;
    float s = 0.f;
    #pragma unroll
    for (int o = lane; o < 64; o += 32)
        s += g_WX[(size_t)n * FDIM + h * 64 + o] * attn[h * 128 + 64 + o];
    #pragma unroll
    for (int off = 16; off > 0; off >>= 1)
        s += __shfl_xor_sync(0xFFFFFFFFu, s, off);
    if (lane == 0) g_s2[h * NROW + n] = s;
}

__global__ void k_max() {
    __shared__ float sm[256];
    int h = blockIdx.x;
    float m = -1e30f;
    for (int i = threadIdx.x; i < NROW; i += 256)
        m = fmaxf(m, g_s2[h * NROW + i]);
    sm[threadIdx.x] = m;
    __syncthreads();
    for (int s = 128; s > 0; s >>= 1) {
        if (threadIdx.x < s) sm[threadIdx.x] = fmaxf(sm[threadIdx.x], sm[threadIdx.x + s]);
        __syncthreads();
    }
    if (threadIdx.x == 0) g_mx[h] = sm[0];
}

__global__ void k_buildB() {
    int n = blockIdx.y;
    int c = blockIdx.x * 128 + threadIdx.x;   // grid (5, 8192), block 128 -> c in [0,640)
    __half v;
    if (c < 512) {
        int h = c >> 6;
        float w = __expf(g_s2[h * NROW + n] - g_mx[h]);
        v = __float2half_rn(w * g_WX[(size_t)n * FDIM + c]);
    } else if (c < 520) {
        int h = c - 512;
        v = __float2half_rn(__expf(g_s2[h * NROW + n] - g_mx[h]));
    } else {
        v = __float2half_rn(0.f);
    }
    g_B[(size_t)n * NB + c] = v;
}

__global__ void k_convA(const float* __restrict__ A) {
    size_t i = (size_t)blockIdx.x * 256 + threadIdx.x;   // over 16M float4
    float4 v = reinterpret_cast<const float4*>(A)[i];
    __half2* dst = reinterpret_cast<__half2*>(g_A16);
    dst[i * 2]     = __floats2half2_rn(v.x, v.y);
    dst[i * 2 + 1] = __floats2half2_rn(v.z, v.w);
}

__global__ void k_final(float* __restrict__ out) {
    int n = blockIdx.y;
    int c = blockIdx.x * 128 + threadIdx.x;   // grid (4, 8192), block 128 -> c in [0,512)
    int h = c >> 6;
    float num = g_C[(size_t)n * NB + c];
    float den = g_C[(size_t)n * NB + 512 + h];
    float r = num / den;
    out[(size_t)n * FDIM + c] = r > 0.f ? r : 0.f;
}

// ------------------------- fp16 mma GEMM -------------------------
// C[M,N] = A[M,K](fp16, ld=K) @ B[K,N](fp16, ld=N), fp32 accumulate/output (ld=N).
// BM=128, BN=128, BK=32, 8 warps (2x4), warp tile 64x32, m16n8k16.
__global__ __launch_bounds__(256, 2)
void k_gemm(const __half* __restrict__ A, const __half* __restrict__ B,
            float* __restrict__ C, int M, int N, int K)
{
    constexpr int BM = 128, BN = 128, BK = 32;
    __shared__ __half sA[2][BM][BK + 8];   // row stride 40 halves (80B) -> conflict-free
    __shared__ __half sB[2][BK][BN + 8];   // row stride 136 halves (272B) -> conflict-free

    const int tid = threadIdx.x;
    const int m0 = blockIdx.y * BM;
    const int n0 = blockIdx.x * BN;
    const int KT = K / BK;

    float acc[4][4][4];
    #pragma unroll
    for (int a = 0; a < 4; a++)
        #pragma unroll
        for (int b = 0; b < 4; b++)
            #pragma unroll
            for (int c = 0; c < 4; c++) acc[a][b][c] = 0.f;

    auto load_stage = [&](int kt, int buf) {
        #pragma unroll
        for (int i = 0; i < 2; i++) {      // A: 512 chunks of 8 halves
            int ch = i * 256 + tid;
            int r = ch >> 2, c4 = ch & 3;
            const __half* g = A + (size_t)(m0 + r) * K + (size_t)kt * BK + c4 * 8;
            uint32_t s = (uint32_t)__cvta_generic_to_shared(&sA[buf][r][c4 * 8]);
            asm volatile("cp.async.cg.shared.global [%0], [%1], 16;" :: "r"(s), "l"(g));
        }
        #pragma unroll
        for (int i = 0; i < 2; i++) {      // B: 512 chunks of 8 halves
            int ch = i * 256 + tid;
            int r = ch >> 4, c16 = ch & 15;
            const __half* g = B + (size_t)(kt * BK + r) * N + n0 + c16 * 8;
            uint32_t s = (uint32_t)__cvta_generic_to_shared(&sB[buf][r][c16 * 8]);
            asm volatile("cp.async.cg.shared.global [%0], [%1], 16;" :: "r"(s), "l"(g));
        }
    };

    load_stage(0, 0);
    asm volatile("cp.async.commit_group;");
    load_stage(1, 1);
    asm volatile("cp.async.commit_group;");

    const int warp = tid >> 5, lane = tid & 31;
    const int wm = warp >> 2, wn = warp & 3;       // 2 x 4 warp grid
    const int lr = lane & 15, lc = (lane >> 4) * 8;
    const int l4 = lane & 3,  lg = lane >> 2;

    for (int kt = 0; kt < KT; kt++) {
        asm volatile("cp.async.wait_group 1;");
        __syncthreads();
        int buf = kt & 1;
        #pragma unroll
        for (int ks = 0; ks < 2; ks++) {
            uint32_t af[4][4], bf[4][2];
            #pragma unroll
            for (int mi = 0; mi < 4; mi++) {
                uint32_t s = (uint32_t)__cvta_generic_to_shared(
                    &sA[buf][wm * 64 + mi * 16 + lr][ks * 16 + lc]);
                asm volatile("ldmatrix.sync.aligned.m8n8.x4.shared.b16 {%0,%1,%2,%3}, [%4];"
                             : "=r"(af[mi][0]), "=r"(af[mi][1]), "=r"(af[mi][2]), "=r"(af[mi][3])
                             : "r"(s));
            }
            #pragma unroll
            for (int nj = 0; nj < 2; nj++) {
                uint32_t s = (uint32_t)__cvta_generic_to_shared(
                    &sB[buf][ks * 16 + lr][wn * 32 + nj * 16 + lc]);
                asm volatile("ldmatrix.sync.aligned.m8n8.x4.trans.shared.b16 {%0,%1,%2,%3}, [%4];"
                             : "=r"(bf[nj * 2][0]), "=r"(bf[nj * 2][1]),
                               "=r"(bf[nj * 2 + 1][0]), "=r"(bf[nj * 2 + 1][1])
                             : "r"(s));
            }
            #pragma unroll
            for (int mi = 0; mi < 4; mi++)
                #pragma unroll
                for (int ni = 0; ni < 4; ni++)
                    asm volatile(
                        "mma.sync.aligned.m16n8k16.row.col.f32.f16.f16.f32 "
                        "{%0,%1,%2,%3}, {%4,%5,%6,%7}, {%8,%9}, {%0,%1,%2,%3};"
                        : "+f"(acc[mi][ni][0]), "+f"(acc[mi][ni][1]),
                          "+f"(acc[mi][ni][2]), "+f"(acc[mi][ni][3])
                        : "r"(af[mi][0]), "r"(af[mi][1]), "r"(af[mi][2]), "r"(af[mi][3]),
                          "r"(bf[ni][0]), "r"(bf[ni][1]));
        }
        __syncthreads();
        if (kt + 2 < KT) load_stage(kt + 2, buf);
        asm volatile("cp.async.commit_group;");
    }

    #pragma unroll
    for (int mi = 0; mi < 4; mi++) {
        int r0 = m0 + wm * 64 + mi * 16 + lg;
        #pragma unroll
        for (int ni = 0; ni < 4; ni++) {
            int c0 = n0 + wn * 32 + ni * 8 + l4 * 2;
            *reinterpret_cast<float2*>(&C[(size_t)r0 * N + c0]) =
                make_float2(acc[mi][ni][0], acc[mi][ni][1]);
            *reinterpret_cast<float2*>(&C[(size_t)(r0 + 8) * N + c0]) =
                make_float2(acc[mi][ni][2], acc[mi][ni][3]);
        }
    }
}

// ------------------------- launcher -------------------------
extern "C" void kernel_launch(void* const* d_in, const int* in_sizes, int n_in,
                              void* d_out, int out_size)
{
    const float* X    = (const float*)d_in[0];
    const float* A    = (const float*)d_in[1];
    const float* kern = (const float*)d_in[2];
    const float* attn = (const float*)d_in[3];
    float* out = (float*)d_out;

    void *pXc, *pWc, *pWX, *pA16, *pB, *pC;
    cudaGetSymbolAddress(&pXc,  g_Xc);
    cudaGetSymbolAddress(&pWc,  g_Wc);
    cudaGetSymbolAddress(&pWX,  g_WX);
    cudaGetSymbolAddress(&pA16, g_A16);
    cudaGetSymbolAddress(&pB,   g_B);
    cudaGetSymbolAddress(&pC,   g_C);

    // prologue: split-fp16 operands, WX GEMM, scores
    k_prepX<<<(NROW * FDIM) / 256, 256>>>(X);
    k_prepW<<<(FDIM * FDIM) / 256, 256>>>(kern);
    k_gemm<<<dim3(FDIM / 128, NROW / 128), 256>>>(
        (const __half*)pXc, (const __half*)pWc, (float*)pWX, NROW, FDIM, KC);
    k_s2<<<NROW, 256>>>(attn);
    k_max<<<8, 256>>>();
    k_buildB<<<dim3(NB / 128, NROW), 128>>>();

    // A -> fp16 (exact), main GEMM, divide + relu
    k_convA<<<(int)(((size_t)NROW * NROW / 4) / 256), 256>>>(A);
    k_gemm<<<dim3(NB / 128, NROW / 128), 256>>>(
        (const __half*)pA16, (const __half*)pB, (float*)pC, NROW, NB, NROW);
    k_final<<<dim3(FDIM / 128, NROW), 128>>>(out);
}

// round 5
// speedup vs baseline: 1.2265x; 1.2265x over previous
#include <cuda_runtime.h>
#include <cuda_fp16.h>
#include <cstdint>

#define NROW 8192
#define FDIM 512
#define LDBM 520          // B cols: 512 feats + 8 den

// ------------------------- scratch -------------------------
__device__ __half g_X16[(size_t)NROW * FDIM];
__device__ __half g_Wt [(size_t)FDIM * FDIM];   // Wt[f][c], c=h*64+o
__device__ float  g_WX [(size_t)NROW * FDIM];
__device__ float  g_s2 [8 * NROW];
__device__ float  g_mx [8];
__device__ __half g_B  [(size_t)NROW * LDBM];   // B[j][c]: w*WX (c<512), w (512..519)

// ------------------------- templated mma.sync GEMM -------------------------
// C[m0+128, n0+128] = A[M,KLEN] @ B[k][n].  CONV: A is fp32, converted inline.
// DEN: B has 8 extra cols (512..519) accumulated by wn==0 warps; epilogue
// writes relu(acc * (1/den)) straight to C (stride 512).
template<int KLEN, int LDBg, bool CONV, bool DEN>
__global__ __launch_bounds__(256, 2)
void k_mm(const void* Ag_, const __half* __restrict__ Bg, float* __restrict__ Cg)
{
    constexpr int NKT    = KLEN / 32;
    constexpr int A32_SZ = 128 * 32 * 4;              // 16384
    constexpr int A16_SZ = 128 * 40 * 2;              // 10240 (stride 40 halves)
    constexpr int B_SZ   = 32 * 136 * 2;              // 8704  (stride 136 halves)
    constexpr int OFF_A16 = CONV ? 3 * A32_SZ : 0;
    constexpr int OFF_B   = OFF_A16 + (CONV ? 2 : 4) * A16_SZ;
    constexpr int OFF_DEN = OFF_B + 4 * B_SZ;

    extern __shared__ char smem[];
    const uint32_t sbase = (uint32_t)__cvta_generic_to_shared(smem);

    const int tid = threadIdx.x;
    const int wid = tid >> 5, lane = tid & 31;
    const int wm = wid & 1, wn = wid >> 1;            // wn0 warps on SMSP 0,1
    const int lr = lane & 15, lc = (lane >> 4) * 8;
    const int l4 = lane & 3,  lg = lane >> 2;
    const int m0 = blockIdx.y * 128, n0 = blockIdx.x * 128;

    const float*  A32g = (const float*)Ag_;
    const __half* A16g = (const __half*)Ag_;

    float acc[4][4][4];
    #pragma unroll
    for (int a = 0; a < 4; a++)
        #pragma unroll
        for (int b = 0; b < 4; b++)
            #pragma unroll
            for (int c = 0; c < 4; c++) acc[a][b][c] = 0.f;
    float accD[4][4];
    if (DEN) {
        #pragma unroll
        for (int a = 0; a < 4; a++)
            #pragma unroll
            for (int c = 0; c < 4; c++) accD[a][c] = 0.f;
    }

    auto load_stage = [&](int kt) {
        if (CONV) {
            uint32_t sa = sbase + (kt % 3) * A32_SZ;
            const float* g0 = A32g + (size_t)m0 * KLEN + (size_t)kt * 32;
            #pragma unroll
            for (int i = 0; i < 4; i++) {              // 1024 16B chunks
                int ch = i * 256 + tid;
                int r = ch >> 3, c4 = ch & 7;
                asm volatile("cp.async.cg.shared.global [%0], [%1], 16;"
                             :: "r"(sa + r * 128 + c4 * 16),
                                "l"(g0 + (size_t)r * KLEN + c4 * 4));
            }
        } else {
            uint32_t sa = sbase + OFF_A16 + (kt & 3) * A16_SZ;
            const __half* g0 = A16g + (size_t)m0 * KLEN + (size_t)kt * 32;
            #pragma unroll
            for (int i = 0; i < 2; i++) {              // 512 16B chunks
                int ch = i * 256 + tid;
                int r = ch >> 2, c8 = ch & 3;
                asm volatile("cp.async.cg.shared.global [%0], [%1], 16;"
                             :: "r"(sa + r * 80 + c8 * 16),
                                "l"(g0 + (size_t)r * KLEN + c8 * 8));
            }
        }
        uint32_t sb = sbase + OFF_B + (kt & 3) * B_SZ;
        const __half* gb = Bg + (size_t)kt * 32 * LDBg;
        #pragma unroll
        for (int i = 0; i < (DEN ? 3 : 2); i++) {
            int ch = i * 256 + tid;
            if (!DEN || ch < 32 * 17) {
                int r, cc;
                if (DEN) { r = ch / 17; cc = ch % 17; }
                else     { r = ch >> 4; cc = ch & 15; }
                int gcol = (cc < 16) ? (n0 + cc * 8) : 512;
                asm volatile("cp.async.cg.shared.global [%0], [%1], 16;"
                             :: "r"(sb + r * 272 + cc * 16),
                                "l"(gb + (size_t)r * LDBg + gcol));
            }
        }
    };

    auto convert = [&](int kt) {                       // A32[kt%3] -> A16[kt&1]
        const float* s = (const float*)(smem + (kt % 3) * A32_SZ) + tid * 16;
        float4 v0 = ((const float4*)s)[0];
        float4 v1 = ((const float4*)s)[1];
        float4 v2 = ((const float4*)s)[2];
        float4 v3 = ((const float4*)s)[3];
        union { uint4 u; __half2 h[4]; } p0, p1;
        p0.h[0] = __floats2half2_rn(v0.x, v0.y);
        p0.h[1] = __floats2half2_rn(v0.z, v0.w);
        p0.h[2] = __floats2half2_rn(v1.x, v1.y);
        p0.h[3] = __floats2half2_rn(v1.z, v1.w);
        p1.h[0] = __floats2half2_rn(v2.x, v2.y);
        p1.h[1] = __floats2half2_rn(v2.z, v2.w);
        p1.h[2] = __floats2half2_rn(v3.x, v3.y);
        p1.h[3] = __floats2half2_rn(v3.z, v3.w);
        __half* d = (__half*)(smem + OFF_A16 + (kt & 1) * A16_SZ)
                    + (tid >> 1) * 40 + (tid & 1) * 16;
        ((uint4*)d)[0] = p0.u;
        ((uint4*)d)[1] = p1.u;
    };

    auto compute = [&](int kt) {
        const uint32_t a16b = sbase + OFF_A16 + (CONV ? (kt & 1) : (kt & 3)) * A16_SZ;
        const uint32_t bb   = sbase + OFF_B + (kt & 3) * B_SZ;
        #pragma unroll
        for (int ks = 0; ks < 2; ks++) {
            uint32_t af[4][4], bf[4][2], dn[2];
            #pragma unroll
            for (int mi = 0; mi < 4; mi++) {
                uint32_t ad = a16b + ((wm * 64 + mi * 16 + lr) * 40 + ks * 16 + lc) * 2;
                asm volatile("ldmatrix.sync.aligned.m8n8.x4.shared.b16 {%0,%1,%2,%3}, [%4];"
                             : "=r"(af[mi][0]), "=r"(af[mi][1]),
                               "=r"(af[mi][2]), "=r"(af[mi][3]) : "r"(ad));
            }
            #pragma unroll
            for (int nj = 0; nj < 2; nj++) {
                uint32_t bd_ = bb + ((ks * 16 + lr) * 136 + wn * 32 + nj * 16 + lc) * 2;
                asm volatile("ldmatrix.sync.aligned.m8n8.x4.trans.shared.b16 {%0,%1,%2,%3}, [%4];"
                             : "=r"(bf[nj * 2][0]), "=r"(bf[nj * 2][1]),
                               "=r"(bf[nj * 2 + 1][0]), "=r"(bf[nj * 2 + 1][1]) : "r"(bd_));
            }
            if (DEN && wn == 0) {
                uint32_t dd = bb + ((ks * 16 + lr) * 136 + 128) * 2;
                asm volatile("ldmatrix.sync.aligned.m8n8.x2.trans.shared.b16 {%0,%1}, [%2];"
                             : "=r"(dn[0]), "=r"(dn[1]) : "r"(dd));
            }
            #pragma unroll
            for (int mi = 0; mi < 4; mi++) {
                #pragma unroll
                for (int ni = 0; ni < 4; ni++)
                    asm volatile(
                        "mma.sync.aligned.m16n8k16.row.col.f32.f16.f16.f32 "
                        "{%0,%1,%2,%3}, {%4,%5,%6,%7}, {%8,%9}, {%0,%1,%2,%3};"
                        : "+f"(acc[mi][ni][0]), "+f"(acc[mi][ni][1]),
                          "+f"(acc[mi][ni][2]), "+f"(acc[mi][ni][3])
                        : "r"(af[mi][0]), "r"(af[mi][1]), "r"(af[mi][2]), "r"(af[mi][3]),
                          "r"(bf[ni][0]), "r"(bf[ni][1]));
                if (DEN && wn == 0)
                    asm volatile(
                        "mma.sync.aligned.m16n8k16.row.col.f32.f16.f16.f32 "
                        "{%0,%1,%2,%3}, {%4,%5,%6,%7}, {%8,%9}, {%0,%1,%2,%3};"
                        : "+f"(accD[mi][0]), "+f"(accD[mi][1]),
                          "+f"(accD[mi][2]), "+f"(accD[mi][3])
                        : "r"(af[mi][0]), "r"(af[mi][1]), "r"(af[mi][2]), "r"(af[mi][3]),
                          "r"(dn[0]), "r"(dn[1]));
            }
        }
    };

    // preamble: 3 stages in flight
    load_stage(0); asm volatile("cp.async.commit_group;");
    load_stage(1); asm volatile("cp.async.commit_group;");
    load_stage(2); asm volatile("cp.async.commit_group;");
    asm volatile("cp.async.wait_group 1;");            // groups 0,1 done
    __syncthreads();
    if (CONV) { convert(0); __syncthreads(); }

    #pragma unroll 1
    for (int kt = 0; kt < NKT; kt++) {
        compute(kt);
        if (CONV && kt + 1 < NKT) convert(kt + 1);     // stage kt+1 arrived last iter
        if (kt + 3 < NKT) { load_stage(kt + 3); asm volatile("cp.async.commit_group;"); }
        if (CONV) asm volatile("cp.async.wait_group 1;");
        else      asm volatile("cp.async.wait_group 2;");
        __syncthreads();
    }

    // epilogue
    float* ds = (float*)(smem + OFF_DEN);
    if (DEN) {
        if (wn == 0) {
            #pragma unroll
            for (int mi = 0; mi < 4; mi++) {
                int r = wm * 64 + mi * 16 + lg;
                ds[r * 8 + l4 * 2]           = 1.f / accD[mi][0];
                ds[r * 8 + l4 * 2 + 1]       = 1.f / accD[mi][1];
                ds[(r + 8) * 8 + l4 * 2]     = 1.f / accD[mi][2];
                ds[(r + 8) * 8 + l4 * 2 + 1] = 1.f / accD[mi][3];
            }
        }
        __syncthreads();
    }
    #pragma unroll
    for (int mi = 0; mi < 4; mi++) {
        int rl = wm * 64 + mi * 16 + lg;
        int rg = m0 + rl;
        #pragma unroll
        for (int ni = 0; ni < 4; ni++) {
            int c = n0 + wn * 32 + ni * 8 + l4 * 2;
            if (DEN) {
                int h = c >> 6;
                float d0 = ds[rl * 8 + h], d1 = ds[(rl + 8) * 8 + h];
                *reinterpret_cast<float2*>(&Cg[(size_t)rg * 512 + c]) =
                    make_float2(fmaxf(acc[mi][ni][0] * d0, 0.f),
                                fmaxf(acc[mi][ni][1] * d0, 0.f));
                *reinterpret_cast<float2*>(&Cg[(size_t)(rg + 8) * 512 + c]) =
                    make_float2(fmaxf(acc[mi][ni][2] * d1, 0.f),
                                fmaxf(acc[mi][ni][3] * d1, 0.f));
            } else {
                *reinterpret_cast<float2*>(&Cg[(size_t)rg * 512 + c]) =
                    make_float2(acc[mi][ni][0], acc[mi][ni][1]);
                *reinterpret_cast<float2*>(&Cg[(size_t)(rg + 8) * 512 + c]) =
                    make_float2(acc[mi][ni][2], acc[mi][ni][3]);
            }
        }
    }
}

// ------------------------- prep / small kernels -------------------------
__global__ void k_prep(const float* __restrict__ X, const float* __restrict__ kern) {
    int b = blockIdx.x;
    if (b < 4096) {                                    // X -> fp16
        size_t i = (size_t)b * 256 + threadIdx.x;      // over 1M float4
        float4 v = reinterpret_cast<const float4*>(X)[i];
        __half2* d = reinterpret_cast<__half2*>(g_X16);
        d[2 * i]     = __floats2half2_rn(v.x, v.y);
        d[2 * i + 1] = __floats2half2_rn(v.z, v.w);
    } else {                                           // kernels -> Wt[f][c]
        size_t i = (size_t)(b - 4096) * 256 + threadIdx.x;  // over 256K
        int f = (int)(i >> 9), c = (int)(i & 511);
        g_Wt[i] = __float2half_rn(kern[((size_t)(c >> 6) * 512 + f) * 64 + (c & 63)]);
    }
}

__global__ void k_s2(const float* __restrict__ attn) {
    int n = blockIdx.x;
    int h = threadIdx.x >> 5, lane = threadIdx.x & 31;
    float s = 0.f;
    #pragma unroll
    for (int o = lane; o < 64; o += 32)
        s += g_WX[(size_t)n * FDIM + h * 64 + o] * attn[h * 128 + 64 + o];
    #pragma unroll
    for (int off = 16; off > 0; off >>= 1)
        s += __shfl_xor_sync(0xFFFFFFFFu, s, off);
    if (lane == 0) g_s2[h * NROW + n] = s;
}

__global__ void k_max() {
    __shared__ float sm[256];
    int h = blockIdx.x;
    float m = -1e30f;
    for (int i = threadIdx.x; i < NROW; i += 256)
        m = fmaxf(m, g_s2[h * NROW + i]);
    sm[threadIdx.x] = m;
    __syncthreads();
    for (int s = 128; s > 0; s >>= 1) {
        if (threadIdx.x < s) sm[threadIdx.x] = fmaxf(sm[threadIdx.x], sm[threadIdx.x + s]);
        __syncthreads();
    }
    if (threadIdx.x == 0) g_mx[h] = sm[0];
}

__global__ void k_buildB() {                           // grid 8192, block 544
    int n = blockIdx.x;
    int c = threadIdx.x;
    if (c >= LDBM) return;
    int h = (c < 512) ? (c >> 6) : (c - 512);
    float w = __expf(g_s2[h * NROW + n] - g_mx[h]);
    float v = (c < 512) ? w * g_WX[(size_t)n * FDIM + c] : w;
    g_B[(size_t)n * LDBM + c] = __float2half_rn(v);
}

// ------------------------- launcher -------------------------
extern "C" void kernel_launch(void* const* d_in, const int* in_sizes, int n_in,
                              void* d_out, int out_size)
{
    const float* X    = (const float*)d_in[0];
    const float* A    = (const float*)d_in[1];
    const float* kern = (const float*)d_in[2];
    const float* attn = (const float*)d_in[3];
    float* out = (float*)d_out;

    void *pX16, *pWt, *pWX, *pB;
    cudaGetSymbolAddress(&pX16, g_X16);
    cudaGetSymbolAddress(&pWt,  g_Wt);
    cudaGetSymbolAddress(&pWX,  g_WX);
    cudaGetSymbolAddress(&pB,   g_B);

    constexpr int SM_WX   = 4 * (128 * 40 * 2) + 4 * (32 * 136 * 2) + 4096;  // 79872
    constexpr int SM_MAIN = 3 * 16384 + 2 * (128 * 40 * 2) + 4 * (32 * 136 * 2) + 4096; // 108544
    cudaFuncSetAttribute(k_mm<FDIM, FDIM, false, false>,
                         cudaFuncAttributeMaxDynamicSharedMemorySize, SM_WX);
    cudaFuncSetAttribute(k_mm<NROW, LDBM, true, true>,
                         cudaFuncAttributeMaxDynamicSharedMemorySize, SM_MAIN);

    // 1: fp16 operands
    k_prep<<<5120, 256>>>(X, kern);
    // 2: WX = X16 @ Wt   (8192 x 512, K=512)
    k_mm<FDIM, FDIM, false, false><<<dim3(4, 64), 256, SM_WX>>>(pX16, (const __half*)pWt, (float*)pWX);
    // 3-5: scores, per-head max, B build (feats + den cols)
    k_s2<<<NROW, 256>>>(attn);
    k_max<<<8, 256>>>();
    k_buildB<<<NROW, 544>>>();
    // 6: main fused GEMM (inline A conversion, den cols, div+relu epilogue) -> out
    k_mm<NROW, LDBM, true, true><<<dim3(4, 64), 256, SM_MAIN>>>(A, (const __half*)pB, out);
}

// round 6
// speedup vs baseline: 1.5413x; 1.2567x over previous
#include <cuda_runtime.h>
#include <cuda_fp16.h>
#include <cstdint>

#define NROW 8192
#define FDIM 512
#define LDBM 520          // B cols: 512 feats + 8 den

#define SWZ(x) ((x) ^ (((x) >> 3) & 0x70))

// ------------------------- scratch -------------------------
__device__ __half g_X16[(size_t)NROW * FDIM];
__device__ __half g_Wt [(size_t)FDIM * FDIM];   // Wt[f][c], c=h*64+o
__device__ float  g_WX [(size_t)NROW * FDIM];
__device__ float  g_s2 [8 * NROW];
__device__ float  g_mx [8];
__device__ __half g_B  [(size_t)NROW * LDBM];   // B[j][c]: w*WX (c<512), w (512..519)

// ------------------------- templated mma.sync GEMM -------------------------
// C[m0+128, n0+BN] = A[M,KLEN] @ B[k][n].  CONV: A fp32, converted inline
// (swizzled staging). DEN: 8 extra B cols (512..519) accumulated by wn==0
// warps; epilogue writes relu(acc/den) straight to C (stride 512).
template<int KLEN, int LDBg, int BN, bool CONV, bool DEN>
__global__ __launch_bounds__(256, CONV ? 1 : 2)
void k_mm(const void* Ag_, const __half* __restrict__ Bg, float* __restrict__ Cg)
{
    constexpr int NKT    = KLEN / 32;
    constexpr int BSTR   = (BN == 128) ? 136 : 280;   // halves; conflict-free ldmatrix
    constexpr int NI     = BN / 32;                   // 8-col groups per warp
    constexpr int CPR    = BN / 8 + (DEN ? 1 : 0);    // 16B chunks per B row
    constexpr int A32_SZ = 128 * 32 * 4;              // 16384
    constexpr int A16_SZ = 128 * 40 * 2;              // 10240
    constexpr int B_SZ   = 32 * BSTR * 2;
    constexpr int OFF_A16 = CONV ? 4 * A32_SZ : 0;
    constexpr int OFF_B   = OFF_A16 + (CONV ? 2 : 4) * A16_SZ;
    constexpr int OFF_DEN = OFF_B + 4 * B_SZ;

    extern __shared__ char smem[];
    const uint32_t sbase = (uint32_t)__cvta_generic_to_shared(smem);

    const int tid = threadIdx.x;
    const int wid = tid >> 5, lane = tid & 31;
    const int wm = wid & 1, wn = wid >> 1;
    const int lr = lane & 15, lc = (lane >> 4) * 8;
    const int l4 = lane & 3,  lg = lane >> 2;
    const int m0 = blockIdx.y * 128, n0 = blockIdx.x * BN;

    const float*  A32g = (const float*)Ag_;
    const __half* A16g = (const __half*)Ag_;

    float acc[4][NI][4];
    #pragma unroll
    for (int a = 0; a < 4; a++)
        #pragma unroll
        for (int b = 0; b < NI; b++)
            #pragma unroll
            for (int c = 0; c < 4; c++) acc[a][b][c] = 0.f;
    float accD[4][4];
    if (DEN) {
        #pragma unroll
        for (int a = 0; a < 4; a++)
            #pragma unroll
            for (int c = 0; c < 4; c++) accD[a][c] = 0.f;
    }

    auto load_stage = [&](int kt) {
        if (CONV) {
            uint32_t sa = sbase + (kt & 3) * A32_SZ;
            const float* g0 = A32g + (size_t)m0 * KLEN + (size_t)kt * 32;
            #pragma unroll
            for (int i = 0; i < 4; i++) {              // 1024 16B chunks (swizzled)
                int ch = i * 256 + tid;
                int r = ch >> 3, c4 = ch & 7;
                asm volatile("cp.async.cg.shared.global [%0], [%1], 16;"
                             :: "r"(sa + SWZ(r * 128 + c4 * 16)),
                                "l"(g0 + (size_t)r * KLEN + c4 * 4));
            }
        } else {
            uint32_t sa = sbase + OFF_A16 + (kt & 3) * A16_SZ;
            const __half* g0 = A16g + (size_t)m0 * KLEN + (size_t)kt * 32;
            #pragma unroll
            for (int i = 0; i < 2; i++) {              // 512 16B chunks
                int ch = i * 256 + tid;
                int r = ch >> 2, c8 = ch & 3;
                asm volatile("cp.async.cg.shared.global [%0], [%1], 16;"
                             :: "r"(sa + r * 80 + c8 * 16),
                                "l"(g0 + (size_t)r * KLEN + c8 * 8));
            }
        }
        uint32_t sb = sbase + OFF_B + (kt & 3) * B_SZ;
        const __half* gb = Bg + (size_t)kt * 32 * LDBg;
        #pragma unroll
        for (int ch = tid; ch < 32 * CPR; ch += 256) {
            int r = ch / CPR, cc = ch % CPR;
            int gcol = (cc < BN / 8) ? (n0 + cc * 8) : 512;
            asm volatile("cp.async.cg.shared.global [%0], [%1], 16;"
                         :: "r"(sb + r * (BSTR * 2) + cc * 16),
                            "l"(gb + (size_t)r * LDBg + gcol));
        }
    };

    auto convert = [&](int kt) {                       // A32[kt&3] -> A16[kt&1]
        const char* s32 = smem + (kt & 3) * A32_SZ;
        const int row = tid >> 1, half = tid & 1;
        const uint32_t rb = row * 128 + half * 64;
        float4 v[4];
        #pragma unroll
        for (int j = 0; j < 4; j++)
            v[j] = *reinterpret_cast<const float4*>(s32 + SWZ(rb + j * 16));
        union { uint4 u; __half2 h[4]; } p0, p1;
        p0.h[0] = __floats2half2_rn(v[0].x, v[0].y);
        p0.h[1] = __floats2half2_rn(v[0].z, v[0].w);
        p0.h[2] = __floats2half2_rn(v[1].x, v[1].y);
        p0.h[3] = __floats2half2_rn(v[1].z, v[1].w);
        p1.h[0] = __floats2half2_rn(v[2].x, v[2].y);
        p1.h[1] = __floats2half2_rn(v[2].z, v[2].w);
        p1.h[2] = __floats2half2_rn(v[3].x, v[3].y);
        p1.h[3] = __floats2half2_rn(v[3].z, v[3].w);
        __half* d = (__half*)(smem + OFF_A16 + (kt & 1) * A16_SZ) + row * 40 + half * 16;
        ((uint4*)d)[0] = p0.u;
        ((uint4*)d)[1] = p1.u;
    };

    auto compute = [&](int kt) {
        const uint32_t a16b = sbase + OFF_A16 + (CONV ? (kt & 1) : (kt & 3)) * A16_SZ;
        const uint32_t bb   = sbase + OFF_B + (kt & 3) * B_SZ;
        #pragma unroll
        for (int ks = 0; ks < 2; ks++) {
            uint32_t af[4][4], bf[NI][2], dn[2];
            #pragma unroll
            for (int mi = 0; mi < 4; mi++) {
                uint32_t ad = a16b + ((wm * 64 + mi * 16 + lr) * 40 + ks * 16 + lc) * 2;
                asm volatile("ldmatrix.sync.aligned.m8n8.x4.shared.b16 {%0,%1,%2,%3}, [%4];"
                             : "=r"(af[mi][0]), "=r"(af[mi][1]),
                               "=r"(af[mi][2]), "=r"(af[mi][3]) : "r"(ad));
            }
            #pragma unroll
            for (int nj = 0; nj < NI / 2; nj++) {
                uint32_t bd_ = bb + ((ks * 16 + lr) * BSTR + wn * (BN / 4) + nj * 16 + lc) * 2;
                asm volatile("ldmatrix.sync.aligned.m8n8.x4.trans.shared.b16 {%0,%1,%2,%3}, [%4];"
                             : "=r"(bf[nj * 2][0]), "=r"(bf[nj * 2][1]),
                               "=r"(bf[nj * 2 + 1][0]), "=r"(bf[nj * 2 + 1][1]) : "r"(bd_));
            }
            if (DEN && wn == 0) {
                uint32_t dd = bb + ((ks * 16 + lr) * BSTR + BN) * 2;
                asm volatile("ldmatrix.sync.aligned.m8n8.x2.trans.shared.b16 {%0,%1}, [%2];"
                             : "=r"(dn[0]), "=r"(dn[1]) : "r"(dd));
            }
            #pragma unroll
            for (int mi = 0; mi < 4; mi++) {
                #pragma unroll
                for (int ni = 0; ni < NI; ni++)
                    asm volatile(
                        "mma.sync.aligned.m16n8k16.row.col.f32.f16.f16.f32 "
                        "{%0,%1,%2,%3}, {%4,%5,%6,%7}, {%8,%9}, {%0,%1,%2,%3};"
                        : "+f"(acc[mi][ni][0]), "+f"(acc[mi][ni][1]),
                          "+f"(acc[mi][ni][2]), "+f"(acc[mi][ni][3])
                        : "r"(af[mi][0]), "r"(af[mi][1]), "r"(af[mi][2]), "r"(af[mi][3]),
                          "r"(bf[ni][0]), "r"(bf[ni][1]));
                if (DEN && wn == 0)
                    asm volatile(
                        "mma.sync.aligned.m16n8k16.row.col.f32.f16.f16.f32 "
                        "{%0,%1,%2,%3}, {%4,%5,%6,%7}, {%8,%9}, {%0,%1,%2,%3};"
                        : "+f"(accD[mi][0]), "+f"(accD[mi][1]),
                          "+f"(accD[mi][2]), "+f"(accD[mi][3])
                        : "r"(af[mi][0]), "r"(af[mi][1]), "r"(af[mi][2]), "r"(af[mi][3]),
                          "r"(dn[0]), "r"(dn[1]));
            }
        }
    };

    // preamble: 3 stages committed, first stage resident (+converted)
    load_stage(0); asm volatile("cp.async.commit_group;");
    load_stage(1); asm volatile("cp.async.commit_group;");
    load_stage(2); asm volatile("cp.async.commit_group;");
    asm volatile("cp.async.wait_group 2;");
    __syncthreads();
    if (CONV) { convert(0); __syncthreads(); }

    #pragma unroll 1
    for (int kt = 0; kt < NKT; kt++) {
        compute(kt);
        if (kt + 3 < NKT) { load_stage(kt + 3); asm volatile("cp.async.commit_group;"); }
        asm volatile("cp.async.wait_group 2;");        // stage kt+1 resident
        if (CONV && kt + 1 < NKT) convert(kt + 1);
        __syncthreads();
    }

    // epilogue
    float* ds = (float*)(smem + OFF_DEN);
    if (DEN) {
        if (wn == 0) {
            #pragma unroll
            for (int mi = 0; mi < 4; mi++) {
                int r = wm * 64 + mi * 16 + lg;
                ds[r * 8 + l4 * 2]           = 1.f / accD[mi][0];
                ds[r * 8 + l4 * 2 + 1]       = 1.f / accD[mi][1];
                ds[(r + 8) * 8 + l4 * 2]     = 1.f / accD[mi][2];
                ds[(r + 8) * 8 + l4 * 2 + 1] = 1.f / accD[mi][3];
            }
        }
        __syncthreads();
    }
    #pragma unroll
    for (int mi = 0; mi < 4; mi++) {
        int rl = wm * 64 + mi * 16 + lg;
        int rg = m0 + rl;
        #pragma unroll
        for (int ni = 0; ni < NI; ni++) {
            int c = n0 + wn * (BN / 4) + ni * 8 + l4 * 2;
            if (DEN) {
                int h = c >> 6;
                float d0 = ds[rl * 8 + h], d1 = ds[(rl + 8) * 8 + h];
                *reinterpret_cast<float2*>(&Cg[(size_t)rg * 512 + c]) =
                    make_float2(fmaxf(acc[mi][ni][0] * d0, 0.f),
                                fmaxf(acc[mi][ni][1] * d0, 0.f));
                *reinterpret_cast<float2*>(&Cg[(size_t)(rg + 8) * 512 + c]) =
                    make_float2(fmaxf(acc[mi][ni][2] * d1, 0.f),
                                fmaxf(acc[mi][ni][3] * d1, 0.f));
            } else {
                *reinterpret_cast<float2*>(&Cg[(size_t)rg * 512 + c]) =
                    make_float2(acc[mi][ni][0], acc[mi][ni][1]);
                *reinterpret_cast<float2*>(&Cg[(size_t)(rg + 8) * 512 + c]) =
                    make_float2(acc[mi][ni][2], acc[mi][ni][3]);
            }
        }
    }
}

// ------------------------- prep / small kernels -------------------------
__global__ void k_prep(const float* __restrict__ X, const float* __restrict__ kern) {
    int b = blockIdx.x;
    if (b < 4096) {                                    // X -> fp16
        size_t i = (size_t)b * 256 + threadIdx.x;
        float4 v = reinterpret_cast<const float4*>(X)[i];
        __half2* d = reinterpret_cast<__half2*>(g_X16);
        d[2 * i]     = __floats2half2_rn(v.x, v.y);
        d[2 * i + 1] = __floats2half2_rn(v.z, v.w);
    } else {                                           // kernels -> Wt[f][c]
        size_t i = (size_t)(b - 4096) * 256 + threadIdx.x;
        int f = (int)(i >> 9), c = (int)(i & 511);
        g_Wt[i] = __float2half_rn(kern[((size_t)(c >> 6) * 512 + f) * 64 + (c & 63)]);
    }
}

__global__ void k_s2(const float* __restrict__ attn) {
    int n = blockIdx.x;
    int h = threadIdx.x >> 5, lane = threadIdx.x & 31;
    float s = 0.f;
    #pragma unroll
    for (int o = lane; o < 64; o += 32)
        s += g_WX[(size_t)n * FDIM + h * 64 + o] * attn[h * 128 + 64 + o];
    #pragma unroll
    for (int off = 16; off > 0; off >>= 1)
        s += __shfl_xor_sync(0xFFFFFFFFu, s, off);
    if (lane == 0) g_s2[h * NROW + n] = s;
}

__global__ void k_max() {
    __shared__ float sm[256];
    int h = blockIdx.x;
    float m = -1e30f;
    for (int i = threadIdx.x; i < NROW; i += 256)
        m = fmaxf(m, g_s2[h * NROW + i]);
    sm[threadIdx.x] = m;
    __syncthreads();
    for (int s = 128; s > 0; s >>= 1) {
        if (threadIdx.x < s) sm[threadIdx.x] = fmaxf(sm[threadIdx.x], sm[threadIdx.x + s]);
        __syncthreads();
    }
    if (threadIdx.x == 0) g_mx[h] = sm[0];
}

__global__ void k_buildB() {                           // grid 8192, block 544
    int n = blockIdx.x;
    int c = threadIdx.x;
    if (c >= LDBM) return;
    int h = (c < 512) ? (c >> 6) : (c - 512);
    float w = __expf(g_s2[h * NROW + n] - g_mx[h]);
    float v = (c < 512) ? w * g_WX[(size_t)n * FDIM + c] : w;
    g_B[(size_t)n * LDBM + c] = __float2half_rn(v);
}

// ------------------------- launcher -------------------------
extern "C" void kernel_launch(void* const* d_in, const int* in_sizes, int n_in,
                              void* d_out, int out_size)
{
    const float* X    = (const float*)d_in[0];
    const float* A    = (const float*)d_in[1];
    const float* kern = (const float*)d_in[2];
    const float* attn = (const float*)d_in[3];
    float* out = (float*)d_out;

    void *pX16, *pWt, *pWX, *pB;
    cudaGetSymbolAddress(&pX16, g_X16);
    cudaGetSymbolAddress(&pWt,  g_Wt);
    cudaGetSymbolAddress(&pWX,  g_WX);
    cudaGetSymbolAddress(&pB,   g_B);

    constexpr int SM_WX   = 4 * 10240 + 4 * (32 * 136 * 2) + 256;             // 76032
    constexpr int SM_MAIN = 4 * 16384 + 2 * 10240 + 4 * (32 * 280 * 2) + 4096; // 161792
    cudaFuncSetAttribute(k_mm<FDIM, FDIM, 128, false, false>,
                         cudaFuncAttributeMaxDynamicSharedMemorySize, SM_WX);
    cudaFuncSetAttribute(k_mm<NROW, LDBM, 256, true, true>,
                         cudaFuncAttributeMaxDynamicSharedMemorySize, SM_MAIN);

    // 1: fp16 operands
    k_prep<<<5120, 256>>>(X, kern);
    // 2: WX = X16 @ Wt   (8192 x 512, K=512)
    k_mm<FDIM, FDIM, 128, false, false><<<dim3(4, 64), 256, SM_WX>>>(
        pX16, (const __half*)pWt, (float*)pWX);
    // 3-5: scores, per-head max, B build (feats + den cols)
    k_s2<<<NROW, 256>>>(attn);
    k_max<<<8, 256>>>();
    k_buildB<<<NROW, 544>>>();
    // 6: main fused GEMM (inline A conversion, den cols, div+relu epilogue) -> out
    k_mm<NROW, LDBM, 256, true, true><<<dim3(2, 64), 256, SM_MAIN>>>(
        A, (const __half*)pB, out);
}